// round 3
// baseline (speedup 1.0000x reference)
#include <cuda_runtime.h>
#include <cstdint>
#include <cstddef>

#define Hd 128
#define FEAT 512
#define NSRC0 50000
#define NDST0 20000
#define NDST1 4096
#define E0 320000
#define E1 65536

// ---------------- scratch (device globals; no allocations) ----------------
__device__ float g_X[(size_t)NSRC0 * FEAT];      // node-major src features * ns0
__device__ float g_agg0[(size_t)NDST0 * FEAT];
__device__ float g_h0[(size_t)NDST0 * FEAT];     // layer-0 output * ns1
__device__ float g_agg1[(size_t)NDST1 * FEAT];
__device__ float g_h1[(size_t)NDST1 * FEAT];

__device__ int g_cnt_s0[NSRC0];
__device__ int g_cnt_d0[NDST0];
__device__ int g_cnt_s1[NDST0];
__device__ int g_cnt_d1[NDST1];
__device__ float g_ns0[NSRC0];
__device__ float g_nd0[NDST0];
__device__ float g_ns1[NDST0];
__device__ float g_nd1[NDST1];

__device__ int g_off0[NDST0 + 1];
__device__ int g_cur0[NDST0];
__device__ int g_csr0[E0];     // src ids grouped by dst
__device__ int g_off1[NDST1 + 1];
__device__ int g_cur1[NDST1];
__device__ int g_csr1[E1];

// ---------------- degree histograms ----------------
__global__ void k_zero() {
    int i = blockIdx.x * blockDim.x + threadIdx.x;
    if (i < NSRC0) g_cnt_s0[i] = 0;
    if (i < NDST0) { g_cnt_d0[i] = 0; g_cnt_s1[i] = 0; }
    if (i < NDST1) g_cnt_d1[i] = 0;
}

__global__ void k_hist(const int* __restrict__ s0, const int* __restrict__ d0,
                       const int* __restrict__ s1, const int* __restrict__ d1) {
    int i = blockIdx.x * blockDim.x + threadIdx.x;
    if (i < E0) { atomicAdd(&g_cnt_s0[s0[i]], 1); atomicAdd(&g_cnt_d0[d0[i]], 1); }
    if (i < E1) { atomicAdd(&g_cnt_s1[s1[i]], 1); atomicAdd(&g_cnt_d1[d1[i]], 1); }
}

__global__ void k_norms() {
    int i = blockIdx.x * blockDim.x + threadIdx.x;
    if (i < NSRC0) g_ns0[i] = rsqrtf((float)max(g_cnt_s0[i], 1));
    if (i < NDST0) {
        g_nd0[i] = rsqrtf((float)max(g_cnt_d0[i], 1));
        g_ns1[i] = rsqrtf((float)max(g_cnt_s1[i], 1));
    }
    if (i < NDST1) g_nd1[i] = rsqrtf((float)max(g_cnt_d1[i], 1));
}

// ---------------- exclusive scan (one block per graph) ----------------
__global__ void k_scan2() {
    const int* cnt; int* off; int* cur; int n;
    if (blockIdx.x == 0) { cnt = g_cnt_d0; off = g_off0; cur = g_cur0; n = NDST0; }
    else                 { cnt = g_cnt_d1; off = g_off1; cur = g_cur1; n = NDST1; }

    __shared__ int sh[1024];
    __shared__ int carry_s;
    int t = threadIdx.x;
    if (t == 0) carry_s = 0;
    __syncthreads();

    for (int base = 0; base < n; base += 1024) {
        int v = (base + t < n) ? cnt[base + t] : 0;
        sh[t] = v;
        __syncthreads();
        #pragma unroll
        for (int d = 1; d < 1024; d <<= 1) {
            int x = (t >= d) ? sh[t - d] : 0;
            __syncthreads();
            sh[t] += x;
            __syncthreads();
        }
        int incl = sh[t];
        int c = carry_s;
        if (base + t < n) {
            int e = c + incl - v;
            off[base + t] = e;
            cur[base + t] = e;
        }
        __syncthreads();
        if (t == 0) carry_s = c + sh[1023];
        __syncthreads();
    }
    if (t == 0) off[n] = carry_s;
}

__global__ void k_fill(const int* __restrict__ s0, const int* __restrict__ d0,
                       const int* __restrict__ s1, const int* __restrict__ d1) {
    int i = blockIdx.x * blockDim.x + threadIdx.x;
    if (i < E0) { int p = atomicAdd(&g_cur0[d0[i]], 1); g_csr0[p] = s0[i]; }
    if (i < E1) { int p = atomicAdd(&g_cur1[d1[i]], 1); g_csr1[p] = s1[i]; }
}

// ---------------- input transpose [A,H,C,N] -> X[n][(a*2+c)*128+h], * ns0[n] ----------------
__global__ void k_transpose(const float* __restrict__ inf) {
    __shared__ float sh[64][33];
    int fi0 = blockIdx.y * 64;        // 0..448 step 64
    int n0  = blockIdx.x * 32;
    int tx = threadIdx.x;             // 32
    int ty = threadIdx.y;             // 16
    int n = n0 + tx;
    bool nok = n < NSRC0;
    #pragma unroll
    for (int r = ty; r < 64; r += 16)
        sh[r][tx] = nok ? inf[(size_t)(fi0 + r) * NSRC0 + n] : 0.f;
    __syncthreads();
    int a  = fi0 >> 8;
    int h0 = (fi0 & 255) >> 1;
    #pragma unroll
    for (int c = 0; c < 2; c++) {
        for (int nn = ty; nn < 32; nn += 16) {
            int nidx = n0 + nn;
            if (nidx < NSRC0) {
                float s = g_ns0[nidx];
                g_X[(size_t)nidx * FEAT + a * 256 + c * 128 + h0 + tx] = sh[tx * 2 + c][nn] * s;
            }
        }
    }
}

// ---------------- aggregation: warp per dst, full 512-f row ----------------
__global__ void k_agg(const int* __restrict__ off, const int* __restrict__ csr,
                      const float* __restrict__ feat, float* __restrict__ out, int ndst) {
    int w = (blockIdx.x * blockDim.x + threadIdx.x) >> 5;
    int lane = threadIdx.x & 31;
    if (w >= ndst) return;
    int beg = off[w], end = off[w + 1];
    float4 a0 = make_float4(0.f, 0.f, 0.f, 0.f), a1 = a0, a2 = a0, a3 = a0;
    for (int e = beg; e < end; e++) {
        const float4* p = (const float4*)(feat + (size_t)csr[e] * FEAT) + lane;
        float4 v0 = p[0], v1 = p[32], v2 = p[64], v3 = p[96];
        a0.x += v0.x; a0.y += v0.y; a0.z += v0.z; a0.w += v0.w;
        a1.x += v1.x; a1.y += v1.y; a1.z += v1.z; a1.w += v1.w;
        a2.x += v2.x; a2.y += v2.y; a2.z += v2.z; a2.w += v2.w;
        a3.x += v3.x; a3.y += v3.y; a3.z += v3.z; a3.w += v3.w;
    }
    float4* o = (float4*)(out + (size_t)w * FEAT) + lane;
    o[0] = a0; o[32] = a1; o[64] = a2; o[96] = a3;
}

// ---------------- GEMM: C[r][c] = relu((A[r][:]@W)[c]*nd[r>>2] + b[c]) * s2[r>>2] ----------------
// 128-row blocks, full K=N=128, 256 threads, 4x16 microtile, packed f32x2 FMA.
#define SA 132
__global__ void __launch_bounds__(256, 1)
k_gemm(const float* __restrict__ A, const float* __restrict__ Wm,
       const float* __restrict__ bias, const float* __restrict__ nd,
       const float* __restrict__ s2, float* __restrict__ C) {
    extern __shared__ float sh[];
    float* Ash = sh;                 // [128][SA] row-major
    float* Ws  = sh + 128 * SA;      // [128][SA] (k-major, same as W)
    float* bs  = sh + 2 * 128 * SA;  // [128]
    int tid = threadIdx.x;
    size_t row0 = (size_t)blockIdx.x * 128;

    #pragma unroll 4
    for (int i = tid; i < 4096; i += 256) {
        int r = i >> 5, k4 = i & 31;
        float4 v = *((const float4*)(A + (row0 + r) * Hd) + k4);
        *(float4*)(Ash + r * SA + k4 * 4) = v;
    }
    #pragma unroll 4
    for (int i = tid; i < 4096; i += 256) {
        int k = i >> 5, c4 = i & 31;
        *(float4*)(Ws + k * SA + c4 * 4) = *((const float4*)(Wm + k * Hd) + c4);
    }
    if (tid < 128) bs[tid] = bias[tid];
    __syncthreads();

    int rowgrp = tid >> 3;   // 0..31 -> rows rowgrp*4 .. +3
    int colgrp = tid & 7;    // 0..7  -> float4 cols {j*8+colgrp}

    unsigned long long acc[4][8];
    #pragma unroll
    for (int i = 0; i < 4; i++)
        #pragma unroll
        for (int j = 0; j < 8; j++) acc[i][j] = 0ull;

    #pragma unroll 4
    for (int k = 0; k < 128; k++) {
        unsigned long long ap[4];
        #pragma unroll
        for (int i = 0; i < 4; i++) {
            float av = Ash[(rowgrp * 4 + i) * SA + k];
            asm("mov.b64 %0, {%1, %1};" : "=l"(ap[i]) : "f"(av));
        }
        ulonglong2 wv[4];
        #pragma unroll
        for (int j = 0; j < 4; j++)
            wv[j] = *(const ulonglong2*)(Ws + k * SA + (j * 8 + colgrp) * 4);
        #pragma unroll
        for (int i = 0; i < 4; i++) {
            #pragma unroll
            for (int j = 0; j < 4; j++) {
                asm("fma.rn.f32x2 %0, %1, %2, %0;" : "+l"(acc[i][2 * j])     : "l"(ap[i]), "l"(wv[j].x));
                asm("fma.rn.f32x2 %0, %1, %2, %0;" : "+l"(acc[i][2 * j + 1]) : "l"(ap[i]), "l"(wv[j].y));
            }
        }
    }

    #pragma unroll
    for (int i = 0; i < 4; i++) {
        int r = rowgrp * 4 + i;
        size_t grow = row0 + r;
        float scale = nd[grow >> 2];
        float s2v = s2 ? s2[grow >> 2] : 1.f;
        #pragma unroll
        for (int j = 0; j < 4; j++) {
            int c4 = j * 8 + colgrp;
            float4 o;
            asm("mov.b64 {%0, %1}, %2;" : "=f"(o.x), "=f"(o.y) : "l"(acc[i][2 * j]));
            asm("mov.b64 {%0, %1}, %2;" : "=f"(o.z), "=f"(o.w) : "l"(acc[i][2 * j + 1]));
            float4 bb = *(const float4*)(bs + c4 * 4);
            o.x = fmaxf(o.x * scale + bb.x, 0.f) * s2v;
            o.y = fmaxf(o.y * scale + bb.y, 0.f) * s2v;
            o.z = fmaxf(o.z * scale + bb.z, 0.f) * s2v;
            o.w = fmaxf(o.w * scale + bb.w, 0.f) * s2v;
            *(float4*)(C + grow * Hd + c4 * 4) = o;
        }
    }
}

// ---------------- output transpose h1[n][(a*2+c)*128+h] -> out[a][h][c][n] ----------------
__global__ void k_out(const float* __restrict__ h1, float* __restrict__ out) {
    __shared__ float sh[32][33];
    int f0 = blockIdx.y * 32;
    int n0 = blockIdx.x * 32;
    int tx = threadIdx.x, ty = threadIdx.y;  // 32 x 8
    #pragma unroll
    for (int nn = ty; nn < 32; nn += 8)
        sh[nn][tx] = h1[(size_t)(n0 + nn) * FEAT + f0 + tx];
    __syncthreads();
    int a  = f0 >> 8;
    int c  = (f0 >> 7) & 1;
    int h0 = f0 & 127;
    // sh[i][j] = h1[node n0+i][feature f0+j]; we emit (node n0+tx, feature f0+fl)
    #pragma unroll
    for (int fl = ty; fl < 32; fl += 8) {
        int fo = (a * 128 + h0 + fl) * 2 + c;
        out[(size_t)fo * NDST1 + n0 + tx] = sh[tx][fl];
    }
}

// ---------------- launcher ----------------
extern "C" void kernel_launch(void* const* d_in, const int* in_sizes, int n_in,
                              void* d_out, int out_size) {
    const float* in_feat = (const float*)d_in[0];
    const float* W       = (const float*)d_in[1];
    const float* b       = (const float*)d_in[2];
    const int* e0s = (const int*)d_in[3];
    const int* e0d = (const int*)d_in[4];
    const int* e1s = (const int*)d_in[5];
    const int* e1d = (const int*)d_in[6];
    float* out = (float*)d_out;

    void *pX, *pagg0, *ph0, *pagg1, *ph1;
    void *poff0, *pcsr0, *poff1, *pcsr1;
    void *pnd0, *pns1, *pnd1;
    cudaGetSymbolAddress(&pX, g_X);
    cudaGetSymbolAddress(&pagg0, g_agg0);
    cudaGetSymbolAddress(&ph0, g_h0);
    cudaGetSymbolAddress(&pagg1, g_agg1);
    cudaGetSymbolAddress(&ph1, g_h1);
    cudaGetSymbolAddress(&poff0, g_off0);
    cudaGetSymbolAddress(&pcsr0, g_csr0);
    cudaGetSymbolAddress(&poff1, g_off1);
    cudaGetSymbolAddress(&pcsr1, g_csr1);
    cudaGetSymbolAddress(&pnd0, g_nd0);
    cudaGetSymbolAddress(&pns1, g_ns1);
    cudaGetSymbolAddress(&pnd1, g_nd1);

    int smem_bytes = (2 * 128 * SA + 128) * (int)sizeof(float);
    cudaFuncSetAttribute(k_gemm, cudaFuncAttributeMaxDynamicSharedMemorySize, smem_bytes);

    // 1. degrees + norms
    k_zero<<<(NSRC0 + 255) / 256, 256>>>();
    k_hist<<<(E0 + 255) / 256, 256>>>(e0s, e0d, e1s, e1d);
    k_norms<<<(NSRC0 + 255) / 256, 256>>>();

    // 2. CSR build
    k_scan2<<<2, 1024>>>();
    k_fill<<<(E0 + 255) / 256, 256>>>(e0s, e0d, e1s, e1d);

    // 3. transpose input (fold ns0)
    {
        dim3 gr((NSRC0 + 31) / 32, FEAT / 64);
        dim3 bl(32, 16);
        k_transpose<<<gr, bl>>>(in_feat);
    }

    // 4. layer 0: aggregate -> GEMM(+nd0,+b,relu,*ns1)
    k_agg<<<(NDST0 + 7) / 8, 256>>>((const int*)poff0, (const int*)pcsr0,
                                    (const float*)pX, (float*)pagg0, NDST0);
    k_gemm<<<(NDST0 * 4) / 128, 256, smem_bytes>>>((const float*)pagg0, W, b,
                                                   (const float*)pnd0, (const float*)pns1,
                                                   (float*)ph0);

    // 5. layer 1: aggregate -> GEMM(+nd1,+b,relu)
    k_agg<<<(NDST1 + 7) / 8, 256>>>((const int*)poff1, (const int*)pcsr1,
                                    (const float*)ph0, (float*)pagg1, NDST1);
    k_gemm<<<(NDST1 * 4) / 128, 256, smem_bytes>>>((const float*)pagg1, W, b,
                                                   (const float*)pnd1, (const float*)nullptr,
                                                   (float*)ph1);

    // 6. output transpose
    {
        dim3 gr(NDST1 / 32, FEAT / 32);
        dim3 bl(32, 8);
        k_out<<<gr, bl>>>((const float*)ph1, out);
    }
    (void)in_sizes; (void)n_in; (void)out_size;
}